// round 3
// baseline (speedup 1.0000x reference)
#include <cuda_runtime.h>
#include <math.h>

#define NN 100000
#define NE 1600000
#define DD 128

// ---------------- scratch (device globals; no allocation) ----------------
// 16B alignment: these are accessed through float4*.
__device__ alignas(16) float g_agg[(size_t)NN * DD];        // 51.2 MB
__device__ alignas(16) float g_xs[(size_t)3 * NN * DD];     // 153.6 MB (layer outputs / concat)
__device__ alignas(16) int   g_deg[NN];
__device__ alignas(16) int   g_cur[NN];
__device__ alignas(16) int   g_srcs[NE];
__device__ alignas(16) int   g_off[NN + 1];
__device__ int g_is64;

// ---------------- dtype probe: int32 vs int64 edge_index ----------------
// If int64 (values < 2^31), every odd int32 word of the src row is a zero high-half.
// If int32, odd words are random node ids; P(64 words all zero) ~ 1e-320.
__global__ void k_detect(const int* __restrict__ ei32) {
    int lane = threadIdx.x;
    int nz = 0;
#pragma unroll
    for (int i = 0; i < 2; i++) {
        int w = ei32[2 * (lane + 32 * i) + 1];
        nz |= (w != 0);
    }
    unsigned any = __ballot_sync(0xffffffffu, nz);
    if (lane == 0) g_is64 = (any == 0u) ? 1 : 0;
}

// ---------------- CSR build ----------------
__global__ void k_zero() {
    int i = blockIdx.x * blockDim.x + threadIdx.x;
    if (i < NN) g_deg[i] = 0;
}

__global__ void k_hist(const int* __restrict__ ei32) {
    int e = blockIdx.x * blockDim.x + threadIdx.x;
    if (e < NE) {
        int is64 = g_is64;
        unsigned d = is64 ? (unsigned)ei32[2 * (NE + e)] : (unsigned)ei32[NE + e];
        if (d < NN) atomicAdd(&g_deg[d], 1);
    }
}

__global__ void k_scan() {
    __shared__ int s[1024];
    int t = threadIdx.x;
    const int CH = (NN + 1023) / 1024;  // 98
    int base = t * CH;
    int sum = 0;
#pragma unroll 4
    for (int i = 0; i < CH; i++) {
        int idx = base + i;
        if (idx < NN) sum += g_deg[idx];
    }
    s[t] = sum;
    __syncthreads();
    for (int off = 1; off < 1024; off <<= 1) {
        int v = (t >= off) ? s[t - off] : 0;
        __syncthreads();
        s[t] += v;
        __syncthreads();
    }
    int run = (t == 0) ? 0 : s[t - 1];
    for (int i = 0; i < CH; i++) {
        int idx = base + i;
        if (idx < NN) {
            g_off[idx] = run;
            g_cur[idx] = run;
            run += g_deg[idx];
        }
    }
    if (t == 0) g_off[NN] = NE;
}

__global__ void k_scatter(const int* __restrict__ ei32) {
    int e = blockIdx.x * blockDim.x + threadIdx.x;
    if (e < NE) {
        int is64 = g_is64;
        unsigned d    = is64 ? (unsigned)ei32[2 * (NE + e)] : (unsigned)ei32[NE + e];
        unsigned srcv = is64 ? (unsigned)ei32[2 * e]        : (unsigned)ei32[e];
        if (d < NN && srcv < NN) {
            int pos = atomicAdd(&g_cur[d], 1);
            g_srcs[pos] = (int)srcv;
        }
    }
}

// ---------------- aggregation: agg[i] = x[i] + sum_{j in-edges} x[src_j] ----------------
// one warp per node, float4 per lane (32 lanes * 16B = full 512B row, coalesced)
__global__ void k_agg(const float* __restrict__ x0, int layer) {
    int gw = (blockIdx.x * blockDim.x + threadIdx.x) >> 5;
    if (gw >= NN) return;
    int lane = threadIdx.x & 31;
    const float* xin = (layer == 0) ? x0 : (g_xs + (size_t)(layer - 1) * NN * DD);
    const float4* x4 = (const float4*)xin;

    float4 acc = x4[(size_t)gw * 32 + lane];
    int j = g_off[gw];
    int end = g_off[gw + 1];
    for (; j < end; j++) {
        int s = g_srcs[j];
        float4 v = __ldg(&x4[(size_t)s * 32 + lane]);
        acc.x += v.x; acc.y += v.y; acc.z += v.z; acc.w += v.w;
    }
    ((float4*)g_agg)[(size_t)gw * 32 + lane] = acc;
}

// ---------------- fused MLP: out = (relu?)( relu(agg@W1+b1) @ W2 + b2 ) ----------------
__device__ __forceinline__ int aswz(int k, int c) {
    return (c ^ (c >> 3) ^ ((k >> 2) & 7)) & 31;
}

__global__ __launch_bounds__(256, 1)
void k_mlp(const float* __restrict__ W1, const float* __restrict__ b1,
           const float* __restrict__ W2, const float* __restrict__ b2,
           int layer)
{
    extern __shared__ float sm[];
    float* As  = sm;                 // 128*128 floats (swizzled, k-major)
    float* Ws1 = sm + 128 * 128;
    float* Ws2 = Ws1 + 128 * 128;
    float4* As4 = (float4*)As;

    const int tid  = threadIdx.x;
    const int base = blockIdx.x * 128;
    const int m0 = (tid & 15) * 8;
    const int n0 = (tid >> 4) * 8;
    const int ca = m0 >> 2;

    {
        const float4* W1_4 = (const float4*)W1;
        const float4* W2_4 = (const float4*)W2;
        float4* Ws1_4 = (float4*)Ws1;
        float4* Ws2_4 = (float4*)Ws2;
#pragma unroll
        for (int i = 0; i < 16; i++) {
            int idx = tid + i * 256;
            Ws1_4[idx] = W1_4[idx];
            Ws2_4[idx] = W2_4[idx];
        }
    }
    {
        const float4* in4 = (const float4*)g_agg;
        int r0 = tid >> 5;
        int c4 = tid & 31;
#pragma unroll
        for (int it = 0; it < 16; it++) {
            int m = r0 + it * 8;
            float4 v = make_float4(0.f, 0.f, 0.f, 0.f);
            if (base + m < NN) v = in4[(size_t)(base + m) * 32 + c4];
            int c = m >> 2, mb = m & 3;
            int k = c4 * 4;
            As[(k + 0) * 128 + aswz(k + 0, c) * 4 + mb] = v.x;
            As[(k + 1) * 128 + aswz(k + 1, c) * 4 + mb] = v.y;
            As[(k + 2) * 128 + aswz(k + 2, c) * 4 + mb] = v.z;
            As[(k + 3) * 128 + aswz(k + 3, c) * 4 + mb] = v.w;
        }
    }
    __syncthreads();

    float acc[8][8];
#pragma unroll
    for (int i = 0; i < 8; i++)
#pragma unroll
        for (int j = 0; j < 8; j++) acc[i][j] = 0.f;

    // GEMM1: h = agg @ W1
#pragma unroll 2
    for (int k = 0; k < 128; k++) {
        float4 a0 = As4[k * 32 + aswz(k, ca)];
        float4 a1 = As4[k * 32 + aswz(k, ca + 1)];
        const float4* wrow = (const float4*)(Ws1 + k * 128 + n0);
        float4 w0 = wrow[0], w1 = wrow[1];
        float a[8] = {a0.x, a0.y, a0.z, a0.w, a1.x, a1.y, a1.z, a1.w};
        float w[8] = {w0.x, w0.y, w0.z, w0.w, w1.x, w1.y, w1.z, w1.w};
#pragma unroll
        for (int i = 0; i < 8; i++)
#pragma unroll
            for (int j = 0; j < 8; j++) acc[i][j] = fmaf(a[i], w[j], acc[i][j]);
    }

#pragma unroll
    for (int j = 0; j < 8; j++) {
        float bj = __ldg(&b1[n0 + j]);
#pragma unroll
        for (int i = 0; i < 8; i++) acc[i][j] = fmaxf(acc[i][j] + bj, 0.f);
    }

    __syncthreads();
#pragma unroll
    for (int j = 0; j < 8; j++) {
        int k2 = n0 + j;
        As4[k2 * 32 + aswz(k2, ca)]     = make_float4(acc[0][j], acc[1][j], acc[2][j], acc[3][j]);
        As4[k2 * 32 + aswz(k2, ca + 1)] = make_float4(acc[4][j], acc[5][j], acc[6][j], acc[7][j]);
    }
    __syncthreads();

#pragma unroll
    for (int i = 0; i < 8; i++)
#pragma unroll
        for (int j = 0; j < 8; j++) acc[i][j] = 0.f;

    // GEMM2: out = h @ W2
#pragma unroll 2
    for (int k = 0; k < 128; k++) {
        float4 a0 = As4[k * 32 + aswz(k, ca)];
        float4 a1 = As4[k * 32 + aswz(k, ca + 1)];
        const float4* wrow = (const float4*)(Ws2 + k * 128 + n0);
        float4 w0 = wrow[0], w1 = wrow[1];
        float a[8] = {a0.x, a0.y, a0.z, a0.w, a1.x, a1.y, a1.z, a1.w};
        float w[8] = {w0.x, w0.y, w0.z, w0.w, w1.x, w1.y, w1.z, w1.w};
#pragma unroll
        for (int i = 0; i < 8; i++)
#pragma unroll
            for (int j = 0; j < 8; j++) acc[i][j] = fmaf(a[i], w[j], acc[i][j]);
    }

    const int relu_out = (layer < 2);
    float bj2[8];
#pragma unroll
    for (int j = 0; j < 8; j++) bj2[j] = __ldg(&b2[n0 + j]);

    float* out = g_xs + (size_t)layer * NN * DD;
    float4* out4 = (float4*)out;
#pragma unroll
    for (int i = 0; i < 8; i++) {
        int m = base + m0 + i;
        if (m < NN) {
            float4 o0, o1;
            o0.x = acc[i][0] + bj2[0]; o0.y = acc[i][1] + bj2[1];
            o0.z = acc[i][2] + bj2[2]; o0.w = acc[i][3] + bj2[3];
            o1.x = acc[i][4] + bj2[4]; o1.y = acc[i][5] + bj2[5];
            o1.z = acc[i][6] + bj2[6]; o1.w = acc[i][7] + bj2[7];
            if (relu_out) {
                o0.x = fmaxf(o0.x, 0.f); o0.y = fmaxf(o0.y, 0.f);
                o0.z = fmaxf(o0.z, 0.f); o0.w = fmaxf(o0.w, 0.f);
                o1.x = fmaxf(o1.x, 0.f); o1.y = fmaxf(o1.y, 0.f);
                o1.z = fmaxf(o1.z, 0.f); o1.w = fmaxf(o1.w, 0.f);
            }
            out4[(size_t)m * 32 + (n0 >> 2)]     = o0;
            out4[(size_t)m * 32 + (n0 >> 2) + 1] = o1;
        }
    }
}

// ---------------- readout: sigmoid(concat(x1,x2,x3) @ Wm + bm) ----------------
__global__ void k_readout(const float* __restrict__ Wm, const float* __restrict__ bm,
                          float* __restrict__ out) {
    int gw = (blockIdx.x * blockDim.x + threadIdx.x) >> 5;
    if (gw >= NN) return;
    int lane = threadIdx.x & 31;
    float acc = 0.f;
#pragma unroll
    for (int l = 0; l < 3; l++) {
        const float4* xs4 = (const float4*)(g_xs + (size_t)l * NN * DD);
        float4 v = xs4[(size_t)gw * 32 + lane];
        float4 w = __ldg(&((const float4*)Wm)[l * 32 + lane]);
        acc += v.x * w.x + v.y * w.y + v.z * w.z + v.w * w.w;
    }
#pragma unroll
    for (int o = 16; o; o >>= 1) acc += __shfl_xor_sync(0xffffffffu, acc, o);
    if (lane == 0) {
        float z = acc + __ldg(bm);
        out[gw] = 1.0f / (1.0f + expf(-z));
    }
}

// ---------------- launch ----------------
extern "C" void kernel_launch(void* const* d_in, const int* in_sizes, int n_in,
                              void* d_out, int out_size) {
    const float* x  = (const float*)d_in[0];
    const int*   ei = (const int*)d_in[1];     // int32 (JAX x64 disabled); probed at runtime
    // d_in[2] = batch (unused, all zeros)
    const float* W1[3] = {(const float*)d_in[3],  (const float*)d_in[7],  (const float*)d_in[11]};
    const float* b1[3] = {(const float*)d_in[4],  (const float*)d_in[8],  (const float*)d_in[12]};
    const float* W2[3] = {(const float*)d_in[5],  (const float*)d_in[9],  (const float*)d_in[13]};
    const float* b2[3] = {(const float*)d_in[6],  (const float*)d_in[10], (const float*)d_in[14]};
    const float* Wm = (const float*)d_in[15];
    const float* bm = (const float*)d_in[16];
    float* out = (float*)d_out;

    const int SMEM_MLP = 3 * 128 * 128 * (int)sizeof(float);  // 192 KB
    cudaFuncSetAttribute(k_mlp, cudaFuncAttributeMaxDynamicSharedMemorySize, SMEM_MLP);

    // CSR build (deterministic every launch)
    k_detect<<<1, 32>>>(ei);
    k_zero<<<(NN + 255) / 256, 256>>>();
    k_hist<<<(NE + 255) / 256, 256>>>(ei);
    k_scan<<<1, 1024>>>();
    k_scatter<<<(NE + 255) / 256, 256>>>(ei);

    const int AGG_BLOCKS = (NN * 32 + 255) / 256;   // 12500
    const int MLP_BLOCKS = (NN + 127) / 128;        // 782

    for (int l = 0; l < 3; l++) {
        k_agg<<<AGG_BLOCKS, 256>>>(x, l);
        k_mlp<<<MLP_BLOCKS, 256, SMEM_MLP>>>(W1[l], b1[l], W2[l], b2[l], l);
    }
    k_readout<<<AGG_BLOCKS, 256>>>(Wm, bm, out);
}

// round 4
// speedup vs baseline: 1.2366x; 1.2366x over previous
#include <cuda_runtime.h>
#include <math.h>

#define NN 100000
#define NE 1600000
#define DD 128
#define SCAN_BLK 1024
#define NSB ((NN + SCAN_BLK - 1) / SCAN_BLK)   // 98 scan blocks

// ---------------- scratch (device globals; no allocation) ----------------
__device__ alignas(16) float g_agg[(size_t)NN * DD];        // 51.2 MB
__device__ alignas(16) float g_xs[(size_t)3 * NN * DD];     // 153.6 MB
__device__ alignas(16) int   g_deg[NN];
__device__ alignas(16) int   g_cur[NN];
__device__ alignas(16) int   g_srcs[NE];
__device__ alignas(16) int   g_off[NN + 1];
__device__ alignas(16) int   g_bsum[NSB];
__device__ alignas(16) int   g_bpre[NSB];
__device__ int g_is64;

// ---------------- packed f32x2 helpers (Blackwell FFMA2) ----------------
__device__ __forceinline__ unsigned long long pk2(float x, float y) {
    unsigned long long r;
    asm("mov.b64 %0, {%1, %2};" : "=l"(r) : "f"(x), "f"(y));
    return r;
}
__device__ __forceinline__ void fma2(unsigned long long& d, unsigned long long a, unsigned long long b) {
    asm("fma.rn.f32x2 %0, %1, %2, %0;" : "+l"(d) : "l"(a), "l"(b));
}
__device__ __forceinline__ void upk2(float& x, float& y, unsigned long long v) {
    asm("mov.b64 {%0, %1}, %2;" : "=f"(x), "=f"(y) : "l"(v));
}

// ---------------- dtype probe: int32 vs int64 edge_index ----------------
__global__ void k_detect(const int* __restrict__ ei32) {
    int lane = threadIdx.x;
    int nz = 0;
#pragma unroll
    for (int i = 0; i < 2; i++) {
        int w = ei32[2 * (lane + 32 * i) + 1];
        nz |= (w != 0);
    }
    unsigned any = __ballot_sync(0xffffffffu, nz);
    if (lane == 0) g_is64 = (any == 0u) ? 1 : 0;
}

// ---------------- CSR build ----------------
__global__ void k_zero() {
    int i = blockIdx.x * blockDim.x + threadIdx.x;
    if (i < NN) g_deg[i] = 0;
}

__global__ void k_hist(const int* __restrict__ ei32) {
    int e = blockIdx.x * blockDim.x + threadIdx.x;
    if (e < NE) {
        int is64 = g_is64;
        unsigned d = is64 ? (unsigned)ei32[2 * (NE + e)] : (unsigned)ei32[NE + e];
        if (d < NN) atomicAdd(&g_deg[d], 1);
    }
}

// phase 1: per-block sums of g_deg
__global__ void k_scan1() {
    __shared__ int ws[32];
    int i = blockIdx.x * SCAN_BLK + threadIdx.x;
    int v = (i < NN) ? g_deg[i] : 0;
    int s = v;
#pragma unroll
    for (int o = 16; o; o >>= 1) s += __shfl_xor_sync(0xffffffffu, s, o);
    if ((threadIdx.x & 31) == 0) ws[threadIdx.x >> 5] = s;
    __syncthreads();
    if (threadIdx.x < 32) {
        int t = ws[threadIdx.x];
#pragma unroll
        for (int o = 16; o; o >>= 1) t += __shfl_xor_sync(0xffffffffu, t, o);
        if (threadIdx.x == 0) g_bsum[blockIdx.x] = t;
    }
}

// phase 2: exclusive scan of NSB (=98) block sums; one block, 128 threads
__global__ void k_scan2() {
    __shared__ int warp_incl[4];
    int t = threadIdx.x;
    int v = (t < NSB) ? g_bsum[t] : 0;
    int incl = v;
#pragma unroll
    for (int o = 1; o < 32; o <<= 1) {
        int u = __shfl_up_sync(0xffffffffu, incl, o);
        if ((t & 31) >= o) incl += u;
    }
    if ((t & 31) == 31) warp_incl[t >> 5] = incl;
    __syncthreads();
    int base = 0;
#pragma unroll
    for (int w = 0; w < 4; w++)
        if ((t >> 5) > w) base += warp_incl[w];
    incl += base;
    if (t < NSB) g_bpre[t] = incl - v;
    if (t == NSB - 1) g_off[NN] = incl;
}

// phase 3: block-local exclusive scan + global base -> g_off / g_cur
__global__ void k_scan3() {
    __shared__ int s[SCAN_BLK];
    int t = threadIdx.x;
    int i = blockIdx.x * SCAN_BLK + t;
    int v = (i < NN) ? g_deg[i] : 0;
    s[t] = v;
    __syncthreads();
    for (int o = 1; o < SCAN_BLK; o <<= 1) {
        int u = (t >= o) ? s[t - o] : 0;
        __syncthreads();
        s[t] += u;
        __syncthreads();
    }
    if (i < NN) {
        int off = g_bpre[blockIdx.x] + s[t] - v;
        g_off[i] = off;
        g_cur[i] = off;
    }
}

__global__ void k_scatter(const int* __restrict__ ei32) {
    int e = blockIdx.x * blockDim.x + threadIdx.x;
    if (e < NE) {
        int is64 = g_is64;
        unsigned d    = is64 ? (unsigned)ei32[2 * (NE + e)] : (unsigned)ei32[NE + e];
        unsigned srcv = is64 ? (unsigned)ei32[2 * e]        : (unsigned)ei32[e];
        if (d < NN && srcv < NN) {
            int pos = atomicAdd(&g_cur[d], 1);
            g_srcs[pos] = (int)srcv;
        }
    }
}

// ---------------- aggregation ----------------
__global__ void k_agg(const float* __restrict__ x0, int layer) {
    int gw = (blockIdx.x * blockDim.x + threadIdx.x) >> 5;
    if (gw >= NN) return;
    int lane = threadIdx.x & 31;
    const float* xin = (layer == 0) ? x0 : (g_xs + (size_t)(layer - 1) * NN * DD);
    const float4* x4 = (const float4*)xin;

    float4 acc = x4[(size_t)gw * 32 + lane];
    int j = g_off[gw];
    int end = g_off[gw + 1];
    for (; j < end; j++) {
        int s = g_srcs[j];
        float4 v = __ldg(&x4[(size_t)s * 32 + lane]);
        acc.x += v.x; acc.y += v.y; acc.z += v.z; acc.w += v.w;
    }
    ((float4*)g_agg)[(size_t)gw * 32 + lane] = acc;
}

// ---------------- fused MLP with packed f32x2 FMA ----------------
__device__ __forceinline__ int aswz(int k, int c) {
    return (c ^ (c >> 3) ^ ((k >> 2) & 7)) & 31;
}

__global__ __launch_bounds__(256, 1)
void k_mlp(const float* __restrict__ W1, const float* __restrict__ b1,
           const float* __restrict__ W2, const float* __restrict__ b2,
           int layer)
{
    extern __shared__ float sm[];
    float* As  = sm;                 // 128*128 floats (swizzled, k-major)
    float* Ws1 = sm + 128 * 128;
    float* Ws2 = Ws1 + 128 * 128;
    float4* As4 = (float4*)As;

    const int tid  = threadIdx.x;
    const int base = blockIdx.x * 128;
    const int m0 = (tid & 15) * 8;
    const int n0 = (tid >> 4) * 8;
    const int ca = m0 >> 2;

    {
        const float4* W1_4 = (const float4*)W1;
        const float4* W2_4 = (const float4*)W2;
        float4* Ws1_4 = (float4*)Ws1;
        float4* Ws2_4 = (float4*)Ws2;
#pragma unroll
        for (int i = 0; i < 16; i++) {
            int idx = tid + i * 256;
            Ws1_4[idx] = W1_4[idx];
            Ws2_4[idx] = W2_4[idx];
        }
    }
    {
        const float4* in4 = (const float4*)g_agg;
        int r0 = tid >> 5;
        int c4 = tid & 31;
#pragma unroll
        for (int it = 0; it < 16; it++) {
            int m = r0 + it * 8;
            float4 v = make_float4(0.f, 0.f, 0.f, 0.f);
            if (base + m < NN) v = in4[(size_t)(base + m) * 32 + c4];
            int c = m >> 2, mb = m & 3;
            int k = c4 * 4;
            As[(k + 0) * 128 + aswz(k + 0, c) * 4 + mb] = v.x;
            As[(k + 1) * 128 + aswz(k + 1, c) * 4 + mb] = v.y;
            As[(k + 2) * 128 + aswz(k + 2, c) * 4 + mb] = v.z;
            As[(k + 3) * 128 + aswz(k + 3, c) * 4 + mb] = v.w;
        }
    }
    __syncthreads();

    unsigned long long accp[8][4];   // acc[i][2j..2j+1] packed
#pragma unroll
    for (int i = 0; i < 8; i++)
#pragma unroll
        for (int j = 0; j < 4; j++) accp[i][j] = 0ull;

    // GEMM1: h = agg @ W1 (packed FFMA2)
#pragma unroll 2
    for (int k = 0; k < 128; k++) {
        float4 a0 = As4[k * 32 + aswz(k, ca)];
        float4 a1 = As4[k * 32 + aswz(k, ca + 1)];
        const float4* wrow = (const float4*)(Ws1 + k * 128 + n0);
        float4 w0 = wrow[0], w1 = wrow[1];
        unsigned long long wp[4] = {pk2(w0.x, w0.y), pk2(w0.z, w0.w),
                                    pk2(w1.x, w1.y), pk2(w1.z, w1.w)};
        float a[8] = {a0.x, a0.y, a0.z, a0.w, a1.x, a1.y, a1.z, a1.w};
#pragma unroll
        for (int i = 0; i < 8; i++) {
            unsigned long long ap = pk2(a[i], a[i]);
#pragma unroll
            for (int j = 0; j < 4; j++) fma2(accp[i][j], ap, wp[j]);
        }
    }

    // unpack, bias + relu
    float acc[8][8];
#pragma unroll
    for (int i = 0; i < 8; i++)
#pragma unroll
        for (int j = 0; j < 4; j++) upk2(acc[i][2 * j], acc[i][2 * j + 1], accp[i][j]);
#pragma unroll
    for (int j = 0; j < 8; j++) {
        float bj = __ldg(&b1[n0 + j]);
#pragma unroll
        for (int i = 0; i < 8; i++) acc[i][j] = fmaxf(acc[i][j] + bj, 0.f);
    }

    __syncthreads();
#pragma unroll
    for (int j = 0; j < 8; j++) {
        int k2 = n0 + j;
        As4[k2 * 32 + aswz(k2, ca)]     = make_float4(acc[0][j], acc[1][j], acc[2][j], acc[3][j]);
        As4[k2 * 32 + aswz(k2, ca + 1)] = make_float4(acc[4][j], acc[5][j], acc[6][j], acc[7][j]);
    }
    __syncthreads();

#pragma unroll
    for (int i = 0; i < 8; i++)
#pragma unroll
        for (int j = 0; j < 4; j++) accp[i][j] = 0ull;

    // GEMM2: out = h @ W2 (packed FFMA2)
#pragma unroll 2
    for (int k = 0; k < 128; k++) {
        float4 a0 = As4[k * 32 + aswz(k, ca)];
        float4 a1 = As4[k * 32 + aswz(k, ca + 1)];
        const float4* wrow = (const float4*)(Ws2 + k * 128 + n0);
        float4 w0 = wrow[0], w1 = wrow[1];
        unsigned long long wp[4] = {pk2(w0.x, w0.y), pk2(w0.z, w0.w),
                                    pk2(w1.x, w1.y), pk2(w1.z, w1.w)};
        float a[8] = {a0.x, a0.y, a0.z, a0.w, a1.x, a1.y, a1.z, a1.w};
#pragma unroll
        for (int i = 0; i < 8; i++) {
            unsigned long long ap = pk2(a[i], a[i]);
#pragma unroll
            for (int j = 0; j < 4; j++) fma2(accp[i][j], ap, wp[j]);
        }
    }

#pragma unroll
    for (int i = 0; i < 8; i++)
#pragma unroll
        for (int j = 0; j < 4; j++) upk2(acc[i][2 * j], acc[i][2 * j + 1], accp[i][j]);

    const int relu_out = (layer < 2);
    float bj2[8];
#pragma unroll
    for (int j = 0; j < 8; j++) bj2[j] = __ldg(&b2[n0 + j]);

    float* out = g_xs + (size_t)layer * NN * DD;
    float4* out4 = (float4*)out;
#pragma unroll
    for (int i = 0; i < 8; i++) {
        int m = base + m0 + i;
        if (m < NN) {
            float4 o0, o1;
            o0.x = acc[i][0] + bj2[0]; o0.y = acc[i][1] + bj2[1];
            o0.z = acc[i][2] + bj2[2]; o0.w = acc[i][3] + bj2[3];
            o1.x = acc[i][4] + bj2[4]; o1.y = acc[i][5] + bj2[5];
            o1.z = acc[i][6] + bj2[6]; o1.w = acc[i][7] + bj2[7];
            if (relu_out) {
                o0.x = fmaxf(o0.x, 0.f); o0.y = fmaxf(o0.y, 0.f);
                o0.z = fmaxf(o0.z, 0.f); o0.w = fmaxf(o0.w, 0.f);
                o1.x = fmaxf(o1.x, 0.f); o1.y = fmaxf(o1.y, 0.f);
                o1.z = fmaxf(o1.z, 0.f); o1.w = fmaxf(o1.w, 0.f);
            }
            out4[(size_t)m * 32 + (n0 >> 2)]     = o0;
            out4[(size_t)m * 32 + (n0 >> 2) + 1] = o1;
        }
    }
}

// ---------------- readout ----------------
__global__ void k_readout(const float* __restrict__ Wm, const float* __restrict__ bm,
                          float* __restrict__ out) {
    int gw = (blockIdx.x * blockDim.x + threadIdx.x) >> 5;
    if (gw >= NN) return;
    int lane = threadIdx.x & 31;
    float acc = 0.f;
#pragma unroll
    for (int l = 0; l < 3; l++) {
        const float4* xs4 = (const float4*)(g_xs + (size_t)l * NN * DD);
        float4 v = xs4[(size_t)gw * 32 + lane];
        float4 w = __ldg(&((const float4*)Wm)[l * 32 + lane]);
        acc += v.x * w.x + v.y * w.y + v.z * w.z + v.w * w.w;
    }
#pragma unroll
    for (int o = 16; o; o >>= 1) acc += __shfl_xor_sync(0xffffffffu, acc, o);
    if (lane == 0) {
        float z = acc + __ldg(bm);
        out[gw] = 1.0f / (1.0f + expf(-z));
    }
}

// ---------------- launch ----------------
extern "C" void kernel_launch(void* const* d_in, const int* in_sizes, int n_in,
                              void* d_out, int out_size) {
    const float* x  = (const float*)d_in[0];
    const int*   ei = (const int*)d_in[1];
    const float* W1[3] = {(const float*)d_in[3],  (const float*)d_in[7],  (const float*)d_in[11]};
    const float* b1[3] = {(const float*)d_in[4],  (const float*)d_in[8],  (const float*)d_in[12]};
    const float* W2[3] = {(const float*)d_in[5],  (const float*)d_in[9],  (const float*)d_in[13]};
    const float* b2[3] = {(const float*)d_in[6],  (const float*)d_in[10], (const float*)d_in[14]};
    const float* Wm = (const float*)d_in[15];
    const float* bm = (const float*)d_in[16];
    float* out = (float*)d_out;

    const int SMEM_MLP = 3 * 128 * 128 * (int)sizeof(float);  // 192 KB
    cudaFuncSetAttribute(k_mlp, cudaFuncAttributeMaxDynamicSharedMemorySize, SMEM_MLP);

    // CSR build (deterministic every launch)
    k_detect<<<1, 32>>>(ei);
    k_zero<<<(NN + 255) / 256, 256>>>();
    k_hist<<<(NE + 255) / 256, 256>>>(ei);
    k_scan1<<<NSB, SCAN_BLK>>>();
    k_scan2<<<1, 128>>>();
    k_scan3<<<NSB, SCAN_BLK>>>();
    k_scatter<<<(NE + 255) / 256, 256>>>(ei);

    const int AGG_BLOCKS = (NN * 32 + 255) / 256;   // 12500
    const int MLP_BLOCKS = (NN + 127) / 128;        // 782

    for (int l = 0; l < 3; l++) {
        k_agg<<<AGG_BLOCKS, 256>>>(x, l);
        k_mlp<<<MLP_BLOCKS, 256, SMEM_MLP>>>(W1[l], b1[l], W2[l], b2[l], l);
    }
    k_readout<<<AGG_BLOCKS, 256>>>(Wm, bm, out);
}